// round 15
// baseline (speedup 1.0000x reference)
#include <cuda_runtime.h>
#include <cuda_fp16.h>
#include <math.h>
#include <stdint.h>

// Problem dims
#define BB   4
#define SS   512
#define DD   1024
#define HH   16
#define LL   6
#define FFD  4096
#define VV   32000
#define DKK  64
#define NTOK (BB*SS)   // 2048
#define RS   (3*DD)    // fused qkv row stride (halves)

// ---------------------------------------------------------------------------
// Scratch (device globals — no runtime allocation allowed)
// ---------------------------------------------------------------------------
__device__ float  g_x[NTOK*DD];
__device__ __half g_qkv[NTOK*3*DD];    // fused qkv, fp16
__device__ __half g_hf[NTOK*DD];       // LN out, fp16
__device__ __half g_af[NTOK*DD];       // attention out, fp16
__device__ __half g_ff[NTOK*FFD];      // GELU out, fp16
__device__ __half g_ef[(size_t)VV*DD]; // emb as fp16 (head B)

#define WLAYER (4*DD*DD + 2*DD*FFD)    // fp16 weights per layer (qkv,o,ff1,ff2)
__device__ __half g_wf[(size_t)LL*WLAYER];

__device__ __forceinline__ uint32_t smem_u32(const void* p) {
    uint32_t a;
    asm("{ .reg .u64 tmp; cvta.to.shared.u64 tmp, %1; cvt.u32.u64 %0, tmp; }"
        : "=r"(a) : "l"(p));
    return a;
}

// cp.async helpers
__device__ __forceinline__ void cp_async16(uint32_t dst, const void* src) {
    asm volatile("cp.async.cg.shared.global [%0], [%1], 16;" :: "r"(dst), "l"(src) : "memory");
}
__device__ __forceinline__ void cp_commit() {
    asm volatile("cp.async.commit_group;" ::: "memory");
}
template <int N>
__device__ __forceinline__ void cp_wait() {
    asm volatile("cp.async.wait_group %0;" :: "n"(N) : "memory");
}

__device__ __forceinline__ void ldsm_x4(unsigned& r0, unsigned& r1, unsigned& r2,
                                        unsigned& r3, uint32_t a) {
    asm volatile("ldmatrix.sync.aligned.m8n8.x4.shared.b16 {%0,%1,%2,%3}, [%4];"
                 : "=r"(r0), "=r"(r1), "=r"(r2), "=r"(r3) : "r"(a));
}
__device__ __forceinline__ void ldsm_x4_t(unsigned& r0, unsigned& r1, unsigned& r2,
                                          unsigned& r3, uint32_t a) {
    asm volatile("ldmatrix.sync.aligned.m8n8.x4.trans.shared.b16 {%0,%1,%2,%3}, [%4];"
                 : "=r"(r0), "=r"(r1), "=r"(r2), "=r"(r3) : "r"(a));
}

__device__ __forceinline__ void mma16816h(float* c, const unsigned* a, const unsigned* b) {
    asm volatile(
        "mma.sync.aligned.m16n8k16.row.col.f32.f16.f16.f32 "
        "{%0,%1,%2,%3}, {%4,%5,%6,%7}, {%8,%9}, {%0,%1,%2,%3};\n"
        : "+f"(c[0]), "+f"(c[1]), "+f"(c[2]), "+f"(c[3])
        : "r"(a[0]), "r"(a[1]), "r"(a[2]), "r"(a[3]), "r"(b[0]), "r"(b[1]));
}

// ---------------------------------------------------------------------------
// Embedding + batch-indexed positional encoding (faithful to reference)
// ---------------------------------------------------------------------------
__global__ void embed_kernel(const int* __restrict__ ids,
                             const float* __restrict__ emb,
                             const float* __restrict__ pe,
                             float* __restrict__ x) {
    int row = blockIdx.x;
    int b   = row / SS;
    int id  = ids[row];
    const float4* er = (const float4*)(emb + (size_t)id * DD);
    const float4* pr = (const float4*)(pe  + (size_t)b  * DD);
    float4* xr = (float4*)(x + (size_t)row * DD);
    int i = threadIdx.x;
    float4 e = er[i], p = pr[i];
    xr[i] = make_float4(e.x + p.x, e.y + p.y, e.z + p.z, e.w + p.w);
}

// ---------------------------------------------------------------------------
// Weight conversion: transpose + fp16, vectorized (float4 loads, uint64 stores)
// 256 threads flat; 32x32 tile per block.
// ---------------------------------------------------------------------------
__device__ __forceinline__ void whalf_body(const float* __restrict__ W,
                                           __half* __restrict__ T, int K, int N) {
    __shared__ float tile[32][33];
    int n0 = blockIdx.x * 32, k0 = blockIdx.y * 32;
    int lin = threadIdx.x;               // 0..255
    {
        int k  = lin >> 3;               // 0..31
        int nq = lin & 7;                // 0..7 (x4 floats)
        float4 v = *(const float4*)&W[(size_t)(k0 + k) * N + n0 + nq * 4];
        tile[k][nq * 4 + 0] = v.x;
        tile[k][nq * 4 + 1] = v.y;
        tile[k][nq * 4 + 2] = v.z;
        tile[k][nq * 4 + 3] = v.w;
    }
    __syncthreads();
    {
        int n  = lin >> 3;               // 0..31
        int kq = lin & 7;                // 0..7 (x4 k)
        __half2 p0 = __floats2half2_rn(tile[kq * 4 + 0][n], tile[kq * 4 + 1][n]);
        __half2 p1 = __floats2half2_rn(tile[kq * 4 + 2][n], tile[kq * 4 + 3][n]);
        uint64_t pk = (uint64_t)(*(uint32_t*)&p0) | ((uint64_t)(*(uint32_t*)&p1) << 32);
        *(uint64_t*)&T[(size_t)(n0 + n) * K + k0 + kq * 4] = pk;
    }
}

__global__ void whalf_qkvo_kernel(const float* __restrict__ Wq, const float* __restrict__ Wk,
                                  const float* __restrict__ Wv, const float* __restrict__ Wo,
                                  __half* __restrict__ T) {
    int z = blockIdx.z, l = z >> 2, widx = z & 3;
    const float* W = (widx == 0 ? Wq : widx == 1 ? Wk : widx == 2 ? Wv : Wo)
                     + (size_t)l * DD * DD;
    whalf_body(W, T + (size_t)l * WLAYER + (size_t)widx * DD * DD, DD, DD);
}

__global__ void whalf_ff_kernel(const float* __restrict__ W, __half* __restrict__ T,
                                int K, int N, size_t obase) {
    int l = blockIdx.z;
    whalf_body(W + (size_t)l * K * N, T + (size_t)l * WLAYER + obase, K, N);
}

// emb -> fp16 (vectorized)
__global__ void ehalf_kernel(const float* __restrict__ X, __half* __restrict__ Y, int n4) {
    int i = blockIdx.x * 256 + threadIdx.x;
    if (i < n4) {
        float4 v = ((const float4*)X)[i];
        ((__half2*)Y)[i * 2]     = __floats2half2_rn(v.x, v.y);
        ((__half2*)Y)[i * 2 + 1] = __floats2half2_rn(v.z, v.w);
    }
}

// ---------------------------------------------------------------------------
// LayerNorm: 1 float4/thread, warp-shuffle reduce (single barrier), fp16 out
// ---------------------------------------------------------------------------
__global__ void ln_f16_kernel(const float* __restrict__ x,
                              const float* __restrict__ s,
                              const float* __restrict__ b,
                              __half* __restrict__ y) {
    int row = blockIdx.x;
    int t = threadIdx.x;
    float4 v = ((const float4*)(x + (size_t)row * DD))[t];
    float s1 = v.x + v.y + v.z + v.w;
    float s2 = v.x*v.x + v.y*v.y + v.z*v.z + v.w*v.w;
    #pragma unroll
    for (int o = 16; o > 0; o >>= 1) {
        s1 += __shfl_xor_sync(0xffffffff, s1, o);
        s2 += __shfl_xor_sync(0xffffffff, s2, o);
    }
    __shared__ float a1[8], a2[8];
    if ((t & 31) == 0) { a1[t >> 5] = s1; a2[t >> 5] = s2; }
    __syncthreads();
    float m1 = 0.f, m2 = 0.f;
    #pragma unroll
    for (int i = 0; i < 8; i++) { m1 += a1[i]; m2 += a2[i]; }
    float mean = m1 * (1.0f / DD);
    float var  = m2 * (1.0f / DD) - mean * mean;
    float rstd = rsqrtf(var + 1e-5f);

    float4 sv = ((const float4*)s)[t];
    float4 bv = ((const float4*)b)[t];
    __half2 p0 = __floats2half2_rn((v.x - mean) * rstd * sv.x + bv.x,
                                   (v.y - mean) * rstd * sv.y + bv.y);
    __half2 p1 = __floats2half2_rn((v.z - mean) * rstd * sv.z + bv.z,
                                   (v.w - mean) * rstd * sv.w + bv.w);
    size_t o = (size_t)row * DD + t * 4;
    *(uint32_t*)&y[o]     = *(uint32_t*)&p0;
    *(uint32_t*)&y[o + 2] = *(uint32_t*)&p1;
}

// ---------------------------------------------------------------------------
// fp16 GEMM (NT): C = A[M,K] @ B[N,K]^T
// 128x128 CTA tile, BK=64 (ROWB=144), 256 threads,
// cp.async double-buffer + ldmatrix. K must be a multiple of 64.
// EPI 0: C = AB (+bias)        -> fp32  (head)
// EPI 1: C = Cin + AB + bias   -> fp32  (Wo, FF2 residual)
// EPI 2: gelu(AB + bias)       -> fp16  (FF1)
// EPI 3: C = AB                -> fp16  (QKV)
// ---------------------------------------------------------------------------
#define ROWB 144
#define MATB (128 * ROWB)               // 18432
#define H_STAGEB (2 * MATB)             // 36864
#define SMEM_F16 (2 * H_STAGEB)         // 73728 bytes

template <int EPI>
__global__ __launch_bounds__(256, 2)
void gemm_f16(const __half* __restrict__ A, const __half* __restrict__ B,
              const float* __restrict__ bias, const float* __restrict__ Cin,
              float* __restrict__ Cout, __half* __restrict__ Oh,
              int M, int N, int K) {
    extern __shared__ char smem[];
    uint32_t sb = smem_u32(smem);

    int t = threadIdx.x;
    int wid = t >> 5, lane = t & 31;
    int wm = wid >> 1, wn = wid & 1;
    int group = lane >> 2, tig = lane & 3;
    int m0 = blockIdx.y * 128, n0 = blockIdx.x * 128;

    float acc[2][8][4];
    #pragma unroll
    for (int i = 0; i < 2; i++)
        #pragma unroll
        for (int j = 0; j < 8; j++)
            #pragma unroll
            for (int kk = 0; kk < 4; kk++) acc[i][j][kk] = 0.f;

    const __half* srcs[2] = { A, B };

    auto load_stage = [&](int stage, int kt) {
        uint32_t base = sb + stage * H_STAGEB;
        int kofs = kt << 6;
        #pragma unroll
        for (int j = 0; j < 8; j++) {
            int lin = t + j * 256;           // 0..2047
            int mtx = lin >> 10;
            int c   = lin & 1023;
            int row = c >> 3, q = c & 7;
            int rbase = (mtx == 0) ? m0 : n0;
            const __half* src = srcs[mtx] + (size_t)(rbase + row) * K + kofs + q * 8;
            cp_async16(base + mtx * MATB + row * ROWB + q * 16, src);
        }
        cp_commit();
    };

    uint32_t aRow = (uint32_t)(wm * 32 + (lane & 15)) * ROWB;
    uint32_t aCol = (uint32_t)((lane >> 4) << 3) * 2;
    uint32_t bRowBase = (uint32_t)(wn * 64 + (lane & 7) + ((lane >> 4) << 3)) * ROWB;
    uint32_t bCol = (uint32_t)(((lane >> 3) & 1) << 3) * 2;

    const int nk = K >> 6;   // K-tiles of 64

    load_stage(0, 0);

    for (int i = 0; i < nk; i++) {
        if (i + 1 < nk) { load_stage((i + 1) & 1, i + 1); cp_wait<1>(); }
        else            { cp_wait<0>(); }
        __syncthreads();

        uint32_t stb = sb + (i & 1) * H_STAGEB;
        uint32_t pA = stb + aRow + aCol;
        uint32_t pB = stb + MATB + bRowBase + bCol;

        #pragma unroll
        for (int ks = 0; ks < 4; ks++) {
            uint32_t ko = ks * 32;          // 16 halves = 32 bytes per k-step
            unsigned af[2][4], bf[8][2];
            #pragma unroll
            for (int mt = 0; mt < 2; mt++) {
                ldsm_x4(af[mt][0], af[mt][1], af[mt][2], af[mt][3],
                        pA + (uint32_t)(mt * 16) * ROWB + ko);
            }
            #pragma unroll
            for (int jp = 0; jp < 4; jp++) {
                ldsm_x4(bf[2*jp][0], bf[2*jp][1], bf[2*jp+1][0], bf[2*jp+1][1],
                        pB + (uint32_t)(jp * 16) * ROWB + ko);
            }
            #pragma unroll
            for (int mt = 0; mt < 2; mt++)
                #pragma unroll
                for (int nt = 0; nt < 8; nt++)
                    mma16816h(acc[mt][nt], af[mt], bf[nt]);
        }
        __syncthreads();
    }

    #pragma unroll
    for (int mt = 0; mt < 2; mt++) {
        #pragma unroll
        for (int nt = 0; nt < 8; nt++) {
            int col = n0 + wn * 64 + nt * 8 + tig * 2;
            float b0 = 0.f, b1v = 0.f;
            if (EPI != 3 && bias) { b0 = bias[col]; b1v = bias[col + 1]; }
            #pragma unroll
            for (int half = 0; half < 2; half++) {
                int row = m0 + wm * 32 + mt * 16 + group + half * 8;
                float v0 = acc[mt][nt][half * 2 + 0] + b0;
                float v1 = acc[mt][nt][half * 2 + 1] + b1v;
                size_t o = (size_t)row * N + col;
                if (EPI == 0) {
                    Cout[o] = v0; Cout[o + 1] = v1;
                } else if (EPI == 1) {
                    Cout[o] = Cin[o] + v0; Cout[o + 1] = Cin[o + 1] + v1;
                } else if (EPI == 2) {
                    float g0 = 0.5f * v0 * (1.0f + erff(v0 * 0.70710678118654752f));
                    float g1 = 0.5f * v1 * (1.0f + erff(v1 * 0.70710678118654752f));
                    __half2 p = __floats2half2_rn(g0, g1);
                    *(uint32_t*)&Oh[o] = *(uint32_t*)&p;
                } else {
                    __half2 p = __floats2half2_rn(v0, v1);
                    *(uint32_t*)&Oh[o] = *(uint32_t*)&p;
                }
            }
        }
    }
}

// ---------------------------------------------------------------------------
// Flash-style HMMA attention. CTA = (64-query tile, b, h); 4 warps x 16 rows.
// K/V tiles of 64 keys, cp.async double-buffered. Online softmax in regs.
// Rows are 64 halves = 128 data bytes; AROWB = 144 (128 + 16 pad).
// ---------------------------------------------------------------------------
#define AROWB 144
#define A_QOFF 0
#define A_TILE (64 * AROWB)            // 9216 bytes per matrix tile
#define A_STG  (2 * A_TILE)            // K+V per stage
#define A_KOFF(s) (A_TILE + (s) * A_STG)
#define A_VOFF(s) (A_TILE + (s) * A_STG + A_TILE)
#define A_SMEM (A_TILE + 2 * A_STG)    // 46080 bytes

__global__ __launch_bounds__(128)
void fattn_kernel(const __half* __restrict__ QKV, __half* __restrict__ O) {
    __shared__ char smem[A_SMEM];
    uint32_t sb = smem_u32(smem);

    int qt = blockIdx.x;               // 0..7 (64-query tiles)
    int bh = blockIdx.y;
    int b  = bh >> 4, h = bh & 15;
    int t  = threadIdx.x;
    int w  = t >> 5, lane = t & 31;
    int group = lane >> 2, tig = lane & 3;

    size_t tokbase = (size_t)(b * SS + qt * 64);

    // ---- prologue: load Q tile + K/V tile 0
    {
        #pragma unroll
        for (int j = 0; j < 4; j++) {      // Q: 512 chunks (64 rows x 8 x 16B)
            int lin = t + j * 128;
            int row = lin >> 3, q = lin & 7;
            const __half* src = QKV + (tokbase + row) * RS + h * DKK + q * 8;
            cp_async16(sb + A_QOFF + row * AROWB + q * 16, src);
        }
        #pragma unroll
        for (int j = 0; j < 8; j++) {      // K,V tile 0: 1024 chunks
            int lin = t + j * 128;
            int mtx = lin >> 9;
            int c   = lin & 511;
            int row = c >> 3, q = c & 7;
            const __half* src = QKV + (size_t)(b * SS + row) * RS + (1 + mtx) * DD + h * DKK + q * 8;
            cp_async16(sb + (mtx == 0 ? A_KOFF(0) : A_VOFF(0)) + row * AROWB + q * 16, src);
        }
        cp_commit();
    }

    // fragment addresses
    uint32_t qAddr = sb + A_QOFF + (uint32_t)(w * 16 + (lane & 15)) * AROWB
                   + (uint32_t)((lane >> 4) << 3) * 2;
    uint32_t kRowSel = (uint32_t)((lane & 7) + ((lane >> 4) << 3)) * AROWB
                     + (uint32_t)(((lane >> 3) & 1) << 3) * 2;
    uint32_t vRowSel = (uint32_t)((lane & 7) + (((lane >> 3) & 1) << 3)) * AROWB
                     + (uint32_t)((lane >> 4) << 3) * 2;

    float oc[8][4];
    #pragma unroll
    for (int i = 0; i < 8; i++)
        #pragma unroll
        for (int j = 0; j < 4; j++) oc[i][j] = 0.f;
    float m0 = -1e30f, m1 = -1e30f, l0 = 0.f, l1 = 0.f;

    const float scale = 0.125f;

    for (int kt = 0; kt <= qt; kt++) {
        if (kt < qt) {
            int s = (kt + 1) & 1;
            #pragma unroll
            for (int j = 0; j < 8; j++) {
                int lin = t + j * 128;
                int mtx = lin >> 9;
                int c   = lin & 511;
                int row = c >> 3, q = c & 7;
                const __half* src = QKV + (size_t)(b * SS + (kt + 1) * 64 + row) * RS
                                  + (1 + mtx) * DD + h * DKK + q * 8;
                cp_async16(sb + (mtx == 0 ? A_KOFF(s) : A_VOFF(s)) + row * AROWB + q * 16, src);
            }
            cp_commit();
            cp_wait<1>();
        } else {
            cp_wait<0>();
        }
        __syncthreads();

        int s = kt & 1;
        uint32_t kBase = sb + A_KOFF(s) + kRowSel;
        uint32_t vBase = sb + A_VOFF(s) + vRowSel;

        // ---- S = Q @ K^T  (16 rows x 64 keys per warp)
        float sc[8][4];
        #pragma unroll
        for (int i = 0; i < 8; i++)
            #pragma unroll
            for (int j = 0; j < 4; j++) sc[i][j] = 0.f;

        unsigned qf[4][4];
        #pragma unroll
        for (int ks = 0; ks < 4; ks++)
            ldsm_x4(qf[ks][0], qf[ks][1], qf[ks][2], qf[ks][3], qAddr + ks * 32);

        #pragma unroll
        for (int jp = 0; jp < 4; jp++) {
            #pragma unroll
            for (int ks = 0; ks < 4; ks++) {
                unsigned b0, b1, b2, b3;
                ldsm_x4(b0, b1, b2, b3, kBase + (uint32_t)(jp * 16) * AROWB + ks * 32);
                unsigned bb0[2] = { b0, b1 }, bb1[2] = { b2, b3 };
                mma16816h(sc[2*jp],     qf[ks], bb0);
                mma16816h(sc[2*jp + 1], qf[ks], bb1);
            }
        }

        // scale + causal mask (diagonal tile only)
        #pragma unroll
        for (int i = 0; i < 8; i++)
            #pragma unroll
            for (int e = 0; e < 4; e++) sc[i][e] *= scale;
        if (kt == qt) {
            #pragma unroll
            for (int i = 0; i < 8; i++) {
                #pragma unroll
                for (int e = 0; e < 4; e++) {
                    int key = i * 8 + 2 * tig + (e & 1);
                    int row = w * 16 + group + ((e >> 1) << 3);
                    if (key > row) sc[i][e] = -1e30f;
                }
            }
        }

        // online softmax (rows group / group+8; reduce over tig lanes)
        float rm0 = -1e30f, rm1 = -1e30f;
        #pragma unroll
        for (int i = 0; i < 8; i++) {
            rm0 = fmaxf(rm0, fmaxf(sc[i][0], sc[i][1]));
            rm1 = fmaxf(rm1, fmaxf(sc[i][2], sc[i][3]));
        }
        rm0 = fmaxf(rm0, __shfl_xor_sync(0xffffffff, rm0, 1));
        rm0 = fmaxf(rm0, __shfl_xor_sync(0xffffffff, rm0, 2));
        rm1 = fmaxf(rm1, __shfl_xor_sync(0xffffffff, rm1, 1));
        rm1 = fmaxf(rm1, __shfl_xor_sync(0xffffffff, rm1, 2));

        float mn0 = fmaxf(m0, rm0), mn1 = fmaxf(m1, rm1);
        float al0 = __expf(m0 - mn0), al1 = __expf(m1 - mn1);

        float rs0 = 0.f, rs1 = 0.f;
        unsigned pa[4][4];
        #pragma unroll
        for (int j = 0; j < 4; j++) {
            float p00 = __expf(sc[2*j][0] - mn0);
            float p01 = __expf(sc[2*j][1] - mn0);
            float p10 = __expf(sc[2*j][2] - mn1);
            float p11 = __expf(sc[2*j][3] - mn1);
            float q00 = __expf(sc[2*j+1][0] - mn0);
            float q01 = __expf(sc[2*j+1][1] - mn0);
            float q10 = __expf(sc[2*j+1][2] - mn1);
            float q11 = __expf(sc[2*j+1][3] - mn1);
            rs0 += p00 + p01 + q00 + q01;
            rs1 += p10 + p11 + q10 + q11;
            __half2 h0 = __floats2half2_rn(p00, p01);
            __half2 h1 = __floats2half2_rn(p10, p11);
            __half2 h2 = __floats2half2_rn(q00, q01);
            __half2 h3 = __floats2half2_rn(q10, q11);
            pa[j][0] = *(unsigned*)&h0;
            pa[j][1] = *(unsigned*)&h1;
            pa[j][2] = *(unsigned*)&h2;
            pa[j][3] = *(unsigned*)&h3;
        }
        rs0 += __shfl_xor_sync(0xffffffff, rs0, 1);
        rs0 += __shfl_xor_sync(0xffffffff, rs0, 2);
        rs1 += __shfl_xor_sync(0xffffffff, rs1, 1);
        rs1 += __shfl_xor_sync(0xffffffff, rs1, 2);

        l0 = l0 * al0 + rs0;
        l1 = l1 * al1 + rs1;
        m0 = mn0; m1 = mn1;

        #pragma unroll
        for (int i = 0; i < 8; i++) {
            oc[i][0] *= al0; oc[i][1] *= al0;
            oc[i][2] *= al1; oc[i][3] *= al1;
        }

        // ---- O += P @ V   (V^T fragments via ldmatrix.trans)
        #pragma unroll
        for (int j = 0; j < 4; j++) {
            #pragma unroll
            for (int np = 0; np < 4; np++) {
                unsigned v0, v1, v2, v3;
                ldsm_x4_t(v0, v1, v2, v3,
                          vBase + (uint32_t)(j * 16) * AROWB + (uint32_t)(np * 16) * 2);
                unsigned vv0[2] = { v0, v1 }, vv1[2] = { v2, v3 };
                mma16816h(oc[2*np],     pa[j], vv0);
                mma16816h(oc[2*np + 1], pa[j], vv1);
            }
        }
        __syncthreads();
    }

    // ---- write output (fp16)
    float inv0 = 1.0f / l0, inv1 = 1.0f / l1;
    size_t r0 = (tokbase + w * 16 + group) * DD + h * DKK;
    size_t r1 = r0 + 8 * DD;
    #pragma unroll
    for (int i = 0; i < 8; i++) {
        int col = i * 8 + 2 * tig;
        __half2 o0 = __floats2half2_rn(oc[i][0] * inv0, oc[i][1] * inv0);
        __half2 o1 = __floats2half2_rn(oc[i][2] * inv1, oc[i][3] * inv1);
        *(uint32_t*)&O[r0 + col] = *(uint32_t*)&o0;
        *(uint32_t*)&O[r1 + col] = *(uint32_t*)&o1;
    }
}

// ---------------------------------------------------------------------------
// Launch
// ---------------------------------------------------------------------------
extern "C" void kernel_launch(void* const* d_in, const int* in_sizes, int n_in,
                              void* d_out, int out_size) {
    (void)in_sizes; (void)n_in; (void)out_size;

    const int*   ids  = (const int*)  d_in[0];
    const float* emb  = (const float*)d_in[1];
    const float* pe   = (const float*)d_in[2];
    const float* Wq   = (const float*)d_in[3];
    const float* Wk   = (const float*)d_in[4];
    const float* Wv   = (const float*)d_in[5];
    const float* Wo   = (const float*)d_in[6];
    const float* bo   = (const float*)d_in[7];
    const float* ln1s = (const float*)d_in[8];
    const float* ln1b = (const float*)d_in[9];
    const float* ln2s = (const float*)d_in[10];
    const float* ln2b = (const float*)d_in[11];
    const float* W1   = (const float*)d_in[12];
    const float* b1   = (const float*)d_in[13];
    const float* W2   = (const float*)d_in[14];
    const float* b2   = (const float*)d_in[15];
    const float* lnfs = (const float*)d_in[16];
    const float* lnfb = (const float*)d_in[17];
    float* out = (float*)d_out;

    float *x;
    __half *qkv, *hf, *af, *ff, *ef, *wf;
    cudaGetSymbolAddress((void**)&x,   g_x);
    cudaGetSymbolAddress((void**)&qkv, g_qkv);
    cudaGetSymbolAddress((void**)&hf,  g_hf);
    cudaGetSymbolAddress((void**)&af,  g_af);
    cudaGetSymbolAddress((void**)&ff,  g_ff);
    cudaGetSymbolAddress((void**)&ef,  g_ef);
    cudaGetSymbolAddress((void**)&wf,  g_wf);

    cudaFuncSetAttribute(gemm_f16<0>, cudaFuncAttributeMaxDynamicSharedMemorySize, SMEM_F16);
    cudaFuncSetAttribute(gemm_f16<1>, cudaFuncAttributeMaxDynamicSharedMemorySize, SMEM_F16);
    cudaFuncSetAttribute(gemm_f16<2>, cudaFuncAttributeMaxDynamicSharedMemorySize, SMEM_F16);
    cudaFuncSetAttribute(gemm_f16<3>, cudaFuncAttributeMaxDynamicSharedMemorySize, SMEM_F16);

    {
        dim3 gQ(DD / 32, DD / 32, LL * 4);
        whalf_qkvo_kernel<<<gQ, 256>>>(Wq, Wk, Wv, Wo, wf);
        dim3 g1(FFD / 32, DD / 32, LL);
        whalf_ff_kernel<<<g1, 256>>>(W1, wf, DD, FFD, (size_t)4 * DD * DD);
        dim3 g2(DD / 32, FFD / 32, LL);
        whalf_ff_kernel<<<g2, 256>>>(W2, wf, FFD, DD, (size_t)4 * DD * DD + (size_t)DD * FFD);
    }
    {
        int n4 = (VV * DD) / 4;
        ehalf_kernel<<<(n4 + 255) / 256, 256>>>(emb, ef, n4);
    }

    embed_kernel<<<NTOK, 256>>>(ids, emb, pe, x);

    dim3 gQKV(3 * DD / 128, NTOK / 128);  // 24 x 16
    dim3 gD(DD / 128, NTOK / 128);        // 8 x 16
    dim3 gF(FFD / 128, NTOK / 128);       // 32 x 16
    dim3 gV(VV / 128, NTOK / 128);        // 250 x 16
    dim3 gA(SS / 64, BB * HH);            // 8 x 64

    for (int l = 0; l < LL; l++) {
        __half* wqkv = wf + (size_t)l * WLAYER;         // [3*DD][DD]
        __half* wo   = wqkv + 3 * DD * DD;              // [DD][DD]
        __half* w1   = wo + DD * DD;                    // [FFD][DD]
        __half* w2   = w1 + (size_t)DD * FFD;           // [DD][FFD]

        ln_f16_kernel<<<NTOK, 256>>>(x, ln1s + l * DD, ln1b + l * DD, hf);
        gemm_f16<3><<<gQKV, 256, SMEM_F16>>>(hf, wqkv, nullptr, nullptr, nullptr, qkv, NTOK, 3 * DD, DD);
        fattn_kernel<<<gA, 128>>>(qkv, af);
        gemm_f16<1><<<gD, 256, SMEM_F16>>>(af, wo, bo + l * DD, x, x, nullptr, NTOK, DD, DD);

        ln_f16_kernel<<<NTOK, 256>>>(x, ln2s + l * DD, ln2b + l * DD, hf);
        gemm_f16<2><<<gF, 256, SMEM_F16>>>(hf, w1, b1 + l * FFD, nullptr, nullptr, ff, NTOK, FFD, DD);
        gemm_f16<1><<<gD, 256, SMEM_F16>>>(ff, w2, b2 + l * DD, x, x, nullptr, NTOK, DD, FFD);
    }

    ln_f16_kernel<<<NTOK, 256>>>(x, lnfs, lnfb, hf);
    gemm_f16<0><<<gV, 256, SMEM_F16>>>(hf, ef, nullptr, nullptr, out, nullptr, NTOK, VV, DD);
}

// round 16
// speedup vs baseline: 1.5258x; 1.5258x over previous
#include <cuda_runtime.h>
#include <cuda_fp16.h>
#include <math.h>
#include <stdint.h>

// Problem dims
#define BB   4
#define SS   512
#define DD   1024
#define HH   16
#define LL   6
#define FFD  4096
#define VV   32000
#define DKK  64
#define NTOK (BB*SS)   // 2048
#define RS   (3*DD)    // fused qkv row stride (halves)

// ---------------------------------------------------------------------------
// Scratch (device globals — no runtime allocation allowed)
// ---------------------------------------------------------------------------
__device__ float  g_x[NTOK*DD];
__device__ __half g_qkv[NTOK*3*DD];    // fused qkv, fp16
__device__ __half g_hf[NTOK*DD];       // LN out, fp16
__device__ __half g_af[NTOK*DD];       // attention out, fp16
__device__ __half g_ff[NTOK*FFD];      // GELU out, fp16
__device__ __half g_ef[(size_t)VV*DD]; // emb as fp16 (head B)

#define WLAYER (4*DD*DD + 2*DD*FFD)    // fp16 weights per layer (qkv,o,ff1,ff2)
__device__ __half g_wf[(size_t)LL*WLAYER];

__device__ __forceinline__ uint32_t smem_u32(const void* p) {
    uint32_t a;
    asm("{ .reg .u64 tmp; cvta.to.shared.u64 tmp, %1; cvt.u32.u64 %0, tmp; }"
        : "=r"(a) : "l"(p));
    return a;
}

// cp.async helpers
__device__ __forceinline__ void cp_async16(uint32_t dst, const void* src) {
    asm volatile("cp.async.cg.shared.global [%0], [%1], 16;" :: "r"(dst), "l"(src) : "memory");
}
__device__ __forceinline__ void cp_commit() {
    asm volatile("cp.async.commit_group;" ::: "memory");
}
template <int N>
__device__ __forceinline__ void cp_wait() {
    asm volatile("cp.async.wait_group %0;" :: "n"(N) : "memory");
}

__device__ __forceinline__ void ldsm_x4(unsigned& r0, unsigned& r1, unsigned& r2,
                                        unsigned& r3, uint32_t a) {
    asm volatile("ldmatrix.sync.aligned.m8n8.x4.shared.b16 {%0,%1,%2,%3}, [%4];"
                 : "=r"(r0), "=r"(r1), "=r"(r2), "=r"(r3) : "r"(a));
}
__device__ __forceinline__ void ldsm_x4_t(unsigned& r0, unsigned& r1, unsigned& r2,
                                          unsigned& r3, uint32_t a) {
    asm volatile("ldmatrix.sync.aligned.m8n8.x4.trans.shared.b16 {%0,%1,%2,%3}, [%4];"
                 : "=r"(r0), "=r"(r1), "=r"(r2), "=r"(r3) : "r"(a));
}

__device__ __forceinline__ void mma16816h(float* c, const unsigned* a, const unsigned* b) {
    asm volatile(
        "mma.sync.aligned.m16n8k16.row.col.f32.f16.f16.f32 "
        "{%0,%1,%2,%3}, {%4,%5,%6,%7}, {%8,%9}, {%0,%1,%2,%3};\n"
        : "+f"(c[0]), "+f"(c[1]), "+f"(c[2]), "+f"(c[3])
        : "r"(a[0]), "r"(a[1]), "r"(a[2]), "r"(a[3]), "r"(b[0]), "r"(b[1]));
}

// ---------------------------------------------------------------------------
// Embedding + batch-indexed positional encoding (faithful to reference)
// ---------------------------------------------------------------------------
__global__ void embed_kernel(const int* __restrict__ ids,
                             const float* __restrict__ emb,
                             const float* __restrict__ pe,
                             float* __restrict__ x) {
    int row = blockIdx.x;
    int b   = row / SS;
    int id  = ids[row];
    const float4* er = (const float4*)(emb + (size_t)id * DD);
    const float4* pr = (const float4*)(pe  + (size_t)b  * DD);
    float4* xr = (float4*)(x + (size_t)row * DD);
    int i = threadIdx.x;
    float4 e = er[i], p = pr[i];
    xr[i] = make_float4(e.x + p.x, e.y + p.y, e.z + p.z, e.w + p.w);
}

// ---------------------------------------------------------------------------
// Weight conversion: transpose + fp16 (half2 stores), merged over layers
// ---------------------------------------------------------------------------
__device__ __forceinline__ void whalf_body(const float* __restrict__ W,
                                           __half* __restrict__ T, int K, int N) {
    __shared__ float tile[32][33];
    int n0 = blockIdx.x * 32, k0 = blockIdx.y * 32;
    int tx = threadIdx.x, ty = threadIdx.y;   // 32 x 8
    #pragma unroll
    for (int i = 0; i < 4; i++)
        tile[ty + i*8][tx] = W[(size_t)(k0 + ty + i*8) * N + n0 + tx];
    __syncthreads();
    int lin = tx + (ty << 5);
    #pragma unroll
    for (int rep = 0; rep < 2; rep++) {
        int idx = lin + rep * 256;
        int n  = idx >> 4;
        int kk = (idx & 15) << 1;
        __half2 p = __floats2half2_rn(tile[kk][n], tile[kk + 1][n]);
        *(__half2*)&T[(size_t)(n0 + n) * K + k0 + kk] = p;
    }
}

__global__ void whalf_qkvo_kernel(const float* __restrict__ Wq, const float* __restrict__ Wk,
                                  const float* __restrict__ Wv, const float* __restrict__ Wo,
                                  __half* __restrict__ T) {
    int z = blockIdx.z, l = z >> 2, widx = z & 3;
    const float* W = (widx == 0 ? Wq : widx == 1 ? Wk : widx == 2 ? Wv : Wo)
                     + (size_t)l * DD * DD;
    whalf_body(W, T + (size_t)l * WLAYER + (size_t)widx * DD * DD, DD, DD);
}

__global__ void whalf_ff_kernel(const float* __restrict__ W, __half* __restrict__ T,
                                int K, int N, size_t obase) {
    int l = blockIdx.z;
    whalf_body(W + (size_t)l * K * N, T + (size_t)l * WLAYER + obase, K, N);
}

// emb -> fp16 (vectorized)
__global__ void ehalf_kernel(const float* __restrict__ X, __half* __restrict__ Y, int n4) {
    int i = blockIdx.x * 256 + threadIdx.x;
    if (i < n4) {
        float4 v = ((const float4*)X)[i];
        ((__half2*)Y)[i * 2]     = __floats2half2_rn(v.x, v.y);
        ((__half2*)Y)[i * 2 + 1] = __floats2half2_rn(v.z, v.w);
    }
}

// ---------------------------------------------------------------------------
// LayerNorm: 1 float4/thread, warp-shuffle reduce (single barrier), fp16 out
// ---------------------------------------------------------------------------
__global__ void ln_f16_kernel(const float* __restrict__ x,
                              const float* __restrict__ s,
                              const float* __restrict__ b,
                              __half* __restrict__ y) {
    int row = blockIdx.x;
    int t = threadIdx.x;
    float4 v = ((const float4*)(x + (size_t)row * DD))[t];
    float s1 = v.x + v.y + v.z + v.w;
    float s2 = v.x*v.x + v.y*v.y + v.z*v.z + v.w*v.w;
    #pragma unroll
    for (int o = 16; o > 0; o >>= 1) {
        s1 += __shfl_xor_sync(0xffffffff, s1, o);
        s2 += __shfl_xor_sync(0xffffffff, s2, o);
    }
    __shared__ float a1[8], a2[8];
    if ((t & 31) == 0) { a1[t >> 5] = s1; a2[t >> 5] = s2; }
    __syncthreads();
    float m1 = 0.f, m2 = 0.f;
    #pragma unroll
    for (int i = 0; i < 8; i++) { m1 += a1[i]; m2 += a2[i]; }
    float mean = m1 * (1.0f / DD);
    float var  = m2 * (1.0f / DD) - mean * mean;
    float rstd = rsqrtf(var + 1e-5f);

    float4 sv = ((const float4*)s)[t];
    float4 bv = ((const float4*)b)[t];
    __half2 p0 = __floats2half2_rn((v.x - mean) * rstd * sv.x + bv.x,
                                   (v.y - mean) * rstd * sv.y + bv.y);
    __half2 p1 = __floats2half2_rn((v.z - mean) * rstd * sv.z + bv.z,
                                   (v.w - mean) * rstd * sv.w + bv.w);
    size_t o = (size_t)row * DD + t * 4;
    *(uint32_t*)&y[o]     = *(uint32_t*)&p0;
    *(uint32_t*)&y[o + 2] = *(uint32_t*)&p1;
}

// ---------------------------------------------------------------------------
// fp16 GEMM (NT): C = A[M,K] @ B[N,K]^T
// 128x128 CTA tile, BK=64 (ROWB=144: 128B data + 16 pad), 256 threads,
// cp.async double-buffer + ldmatrix. K must be a multiple of 64.
// EPI 0: C = AB (+bias)        -> fp32  (head)
// EPI 1: C = Cin + AB + bias   -> fp32  (Wo, FF2 residual)
// EPI 2: gelu(AB + bias)       -> fp16  (FF1)
// EPI 3: C = AB                -> fp16  (QKV)
// ---------------------------------------------------------------------------
#define ROWB 144
#define MATB (128 * ROWB)               // 18432
#define H_STAGEB (2 * MATB)             // 36864
#define SMEM_F16 (2 * H_STAGEB)         // 73728 bytes

template <int EPI>
__global__ __launch_bounds__(256, 2)
void gemm_f16(const __half* __restrict__ A, const __half* __restrict__ B,
              const float* __restrict__ bias, const float* __restrict__ Cin,
              float* __restrict__ Cout, __half* __restrict__ Oh,
              int M, int N, int K) {
    extern __shared__ char smem[];
    uint32_t sb = smem_u32(smem);

    int t = threadIdx.x;
    int wid = t >> 5, lane = t & 31;
    int wm = wid >> 1, wn = wid & 1;
    int group = lane >> 2, tig = lane & 3;
    int m0 = blockIdx.y * 128, n0 = blockIdx.x * 128;

    float acc[2][8][4];
    #pragma unroll
    for (int i = 0; i < 2; i++)
        #pragma unroll
        for (int j = 0; j < 8; j++)
            #pragma unroll
            for (int kk = 0; kk < 4; kk++) acc[i][j][kk] = 0.f;

    const __half* srcs[2] = { A, B };

    auto load_stage = [&](int stage, int kt) {
        uint32_t base = sb + stage * H_STAGEB;
        int kofs = kt << 6;
        #pragma unroll
        for (int j = 0; j < 8; j++) {
            int lin = t + j * 256;           // 0..2047
            int mtx = lin >> 10;
            int c   = lin & 1023;
            int row = c >> 3, q = c & 7;
            int rbase = (mtx == 0) ? m0 : n0;
            const __half* src = srcs[mtx] + (size_t)(rbase + row) * K + kofs + q * 8;
            cp_async16(base + mtx * MATB + row * ROWB + q * 16, src);
        }
        cp_commit();
    };

    uint32_t aRow = (uint32_t)(wm * 32 + (lane & 15)) * ROWB;
    uint32_t aCol = (uint32_t)((lane >> 4) << 3) * 2;
    uint32_t bRowBase = (uint32_t)(wn * 64 + (lane & 7) + ((lane >> 4) << 3)) * ROWB;
    uint32_t bCol = (uint32_t)(((lane >> 3) & 1) << 3) * 2;

    const int nk = K >> 6;   // K-tiles of 64

    load_stage(0, 0);

    for (int i = 0; i < nk; i++) {
        if (i + 1 < nk) { load_stage((i + 1) & 1, i + 1); cp_wait<1>(); }
        else            { cp_wait<0>(); }
        __syncthreads();

        uint32_t stb = sb + (i & 1) * H_STAGEB;
        uint32_t pA = stb + aRow + aCol;
        uint32_t pB = stb + MATB + bRowBase + bCol;

        #pragma unroll
        for (int ks = 0; ks < 4; ks++) {
            uint32_t ko = ks * 32;          // 16 halves = 32 bytes per k-step
            unsigned af[2][4], bf[8][2];
            #pragma unroll
            for (int mt = 0; mt < 2; mt++) {
                ldsm_x4(af[mt][0], af[mt][1], af[mt][2], af[mt][3],
                        pA + (uint32_t)(mt * 16) * ROWB + ko);
            }
            #pragma unroll
            for (int jp = 0; jp < 4; jp++) {
                ldsm_x4(bf[2*jp][0], bf[2*jp][1], bf[2*jp+1][0], bf[2*jp+1][1],
                        pB + (uint32_t)(jp * 16) * ROWB + ko);
            }
            #pragma unroll
            for (int mt = 0; mt < 2; mt++)
                #pragma unroll
                for (int nt = 0; nt < 8; nt++)
                    mma16816h(acc[mt][nt], af[mt], bf[nt]);
        }
        __syncthreads();
    }

    #pragma unroll
    for (int mt = 0; mt < 2; mt++) {
        #pragma unroll
        for (int nt = 0; nt < 8; nt++) {
            int col = n0 + wn * 64 + nt * 8 + tig * 2;
            float b0 = 0.f, b1v = 0.f;
            if (EPI != 3 && bias) { b0 = bias[col]; b1v = bias[col + 1]; }
            #pragma unroll
            for (int half = 0; half < 2; half++) {
                int row = m0 + wm * 32 + mt * 16 + group + half * 8;
                float v0 = acc[mt][nt][half * 2 + 0] + b0;
                float v1 = acc[mt][nt][half * 2 + 1] + b1v;
                size_t o = (size_t)row * N + col;
                if (EPI == 0) {
                    Cout[o] = v0; Cout[o + 1] = v1;
                } else if (EPI == 1) {
                    Cout[o] = Cin[o] + v0; Cout[o + 1] = Cin[o + 1] + v1;
                } else if (EPI == 2) {
                    float g0 = 0.5f * v0 * (1.0f + erff(v0 * 0.70710678118654752f));
                    float g1 = 0.5f * v1 * (1.0f + erff(v1 * 0.70710678118654752f));
                    __half2 p = __floats2half2_rn(g0, g1);
                    *(uint32_t*)&Oh[o] = *(uint32_t*)&p;
                } else {
                    __half2 p = __floats2half2_rn(v0, v1);
                    *(uint32_t*)&Oh[o] = *(uint32_t*)&p;
                }
            }
        }
    }
}

// ---------------------------------------------------------------------------
// Flash-style HMMA attention. CTA = (64-query tile, b, h); 4 warps x 16 rows.
// K/V tiles of 64 keys, cp.async double-buffered. Online softmax in regs.
// Rows are 64 halves = 128 data bytes; AROWB = 144 (128 + 16 pad).
// ---------------------------------------------------------------------------
#define AROWB 144
#define A_QOFF 0
#define A_TILE (64 * AROWB)            // 9216 bytes per matrix tile
#define A_STG  (2 * A_TILE)            // K+V per stage
#define A_KOFF(s) (A_TILE + (s) * A_STG)
#define A_VOFF(s) (A_TILE + (s) * A_STG + A_TILE)
#define A_SMEM (A_TILE + 2 * A_STG)    // 46080 bytes

__global__ __launch_bounds__(128)
void fattn_kernel(const __half* __restrict__ QKV, __half* __restrict__ O) {
    __shared__ char smem[A_SMEM];
    uint32_t sb = smem_u32(smem);

    int qt = blockIdx.x;               // 0..7 (64-query tiles)
    int bh = blockIdx.y;
    int b  = bh >> 4, h = bh & 15;
    int t  = threadIdx.x;
    int w  = t >> 5, lane = t & 31;
    int group = lane >> 2, tig = lane & 3;

    size_t tokbase = (size_t)(b * SS + qt * 64);

    // ---- prologue: load Q tile + K/V tile 0
    {
        #pragma unroll
        for (int j = 0; j < 4; j++) {      // Q: 512 chunks (64 rows x 8 x 16B)
            int lin = t + j * 128;
            int row = lin >> 3, q = lin & 7;
            const __half* src = QKV + (tokbase + row) * RS + h * DKK + q * 8;
            cp_async16(sb + A_QOFF + row * AROWB + q * 16, src);
        }
        #pragma unroll
        for (int j = 0; j < 8; j++) {      // K,V tile 0: 1024 chunks
            int lin = t + j * 128;
            int mtx = lin >> 9;
            int c   = lin & 511;
            int row = c >> 3, q = c & 7;
            const __half* src = QKV + (size_t)(b * SS + row) * RS + (1 + mtx) * DD + h * DKK + q * 8;
            cp_async16(sb + (mtx == 0 ? A_KOFF(0) : A_VOFF(0)) + row * AROWB + q * 16, src);
        }
        cp_commit();
    }

    // fragment addresses
    uint32_t qAddr = sb + A_QOFF + (uint32_t)(w * 16 + (lane & 15)) * AROWB
                   + (uint32_t)((lane >> 4) << 3) * 2;
    uint32_t kRowSel = (uint32_t)((lane & 7) + ((lane >> 4) << 3)) * AROWB
                     + (uint32_t)(((lane >> 3) & 1) << 3) * 2;
    uint32_t vRowSel = (uint32_t)((lane & 7) + (((lane >> 3) & 1) << 3)) * AROWB
                     + (uint32_t)((lane >> 4) << 3) * 2;

    float oc[8][4];
    #pragma unroll
    for (int i = 0; i < 8; i++)
        #pragma unroll
        for (int j = 0; j < 4; j++) oc[i][j] = 0.f;
    float m0 = -1e30f, m1 = -1e30f, l0 = 0.f, l1 = 0.f;

    const float scale = 0.125f;

    for (int kt = 0; kt <= qt; kt++) {
        if (kt < qt) {
            int s = (kt + 1) & 1;
            #pragma unroll
            for (int j = 0; j < 8; j++) {
                int lin = t + j * 128;
                int mtx = lin >> 9;
                int c   = lin & 511;
                int row = c >> 3, q = c & 7;
                const __half* src = QKV + (size_t)(b * SS + (kt + 1) * 64 + row) * RS
                                  + (1 + mtx) * DD + h * DKK + q * 8;
                cp_async16(sb + (mtx == 0 ? A_KOFF(s) : A_VOFF(s)) + row * AROWB + q * 16, src);
            }
            cp_commit();
            cp_wait<1>();
        } else {
            cp_wait<0>();
        }
        __syncthreads();

        int s = kt & 1;
        uint32_t kBase = sb + A_KOFF(s) + kRowSel;
        uint32_t vBase = sb + A_VOFF(s) + vRowSel;

        // ---- S = Q @ K^T  (16 rows x 64 keys per warp)
        float sc[8][4];
        #pragma unroll
        for (int i = 0; i < 8; i++)
            #pragma unroll
            for (int j = 0; j < 4; j++) sc[i][j] = 0.f;

        unsigned qf[4][4];
        #pragma unroll
        for (int ks = 0; ks < 4; ks++)
            ldsm_x4(qf[ks][0], qf[ks][1], qf[ks][2], qf[ks][3], qAddr + ks * 32);

        #pragma unroll
        for (int jp = 0; jp < 4; jp++) {
            #pragma unroll
            for (int ks = 0; ks < 4; ks++) {
                unsigned b0, b1, b2, b3;
                ldsm_x4(b0, b1, b2, b3, kBase + (uint32_t)(jp * 16) * AROWB + ks * 32);
                unsigned bb0[2] = { b0, b1 }, bb1[2] = { b2, b3 };
                mma16816h(sc[2*jp],     qf[ks], bb0);
                mma16816h(sc[2*jp + 1], qf[ks], bb1);
            }
        }

        // scale + causal mask (diagonal tile only)
        #pragma unroll
        for (int i = 0; i < 8; i++)
            #pragma unroll
            for (int e = 0; e < 4; e++) sc[i][e] *= scale;
        if (kt == qt) {
            #pragma unroll
            for (int i = 0; i < 8; i++) {
                #pragma unroll
                for (int e = 0; e < 4; e++) {
                    int key = i * 8 + 2 * tig + (e & 1);
                    int row = w * 16 + group + ((e >> 1) << 3);
                    if (key > row) sc[i][e] = -1e30f;
                }
            }
        }

        // online softmax (rows group / group+8; reduce over tig lanes)
        float rm0 = -1e30f, rm1 = -1e30f;
        #pragma unroll
        for (int i = 0; i < 8; i++) {
            rm0 = fmaxf(rm0, fmaxf(sc[i][0], sc[i][1]));
            rm1 = fmaxf(rm1, fmaxf(sc[i][2], sc[i][3]));
        }
        rm0 = fmaxf(rm0, __shfl_xor_sync(0xffffffff, rm0, 1));
        rm0 = fmaxf(rm0, __shfl_xor_sync(0xffffffff, rm0, 2));
        rm1 = fmaxf(rm1, __shfl_xor_sync(0xffffffff, rm1, 1));
        rm1 = fmaxf(rm1, __shfl_xor_sync(0xffffffff, rm1, 2));

        float mn0 = fmaxf(m0, rm0), mn1 = fmaxf(m1, rm1);
        float al0 = __expf(m0 - mn0), al1 = __expf(m1 - mn1);

        float rs0 = 0.f, rs1 = 0.f;
        unsigned pa[4][4];
        #pragma unroll
        for (int j = 0; j < 4; j++) {
            float p00 = __expf(sc[2*j][0] - mn0);
            float p01 = __expf(sc[2*j][1] - mn0);
            float p10 = __expf(sc[2*j][2] - mn1);
            float p11 = __expf(sc[2*j][3] - mn1);
            float q00 = __expf(sc[2*j+1][0] - mn0);
            float q01 = __expf(sc[2*j+1][1] - mn0);
            float q10 = __expf(sc[2*j+1][2] - mn1);
            float q11 = __expf(sc[2*j+1][3] - mn1);
            rs0 += p00 + p01 + q00 + q01;
            rs1 += p10 + p11 + q10 + q11;
            __half2 h0 = __floats2half2_rn(p00, p01);
            __half2 h1 = __floats2half2_rn(p10, p11);
            __half2 h2 = __floats2half2_rn(q00, q01);
            __half2 h3 = __floats2half2_rn(q10, q11);
            pa[j][0] = *(unsigned*)&h0;
            pa[j][1] = *(unsigned*)&h1;
            pa[j][2] = *(unsigned*)&h2;
            pa[j][3] = *(unsigned*)&h3;
        }
        rs0 += __shfl_xor_sync(0xffffffff, rs0, 1);
        rs0 += __shfl_xor_sync(0xffffffff, rs0, 2);
        rs1 += __shfl_xor_sync(0xffffffff, rs1, 1);
        rs1 += __shfl_xor_sync(0xffffffff, rs1, 2);

        l0 = l0 * al0 + rs0;
        l1 = l1 * al1 + rs1;
        m0 = mn0; m1 = mn1;

        #pragma unroll
        for (int i = 0; i < 8; i++) {
            oc[i][0] *= al0; oc[i][1] *= al0;
            oc[i][2] *= al1; oc[i][3] *= al1;
        }

        // ---- O += P @ V   (V^T fragments via ldmatrix.trans)
        #pragma unroll
        for (int j = 0; j < 4; j++) {
            #pragma unroll
            for (int np = 0; np < 4; np++) {
                unsigned v0, v1, v2, v3;
                ldsm_x4_t(v0, v1, v2, v3,
                          vBase + (uint32_t)(j * 16) * AROWB + (uint32_t)(np * 16) * 2);
                unsigned vv0[2] = { v0, v1 }, vv1[2] = { v2, v3 };
                mma16816h(oc[2*np],     pa[j], vv0);
                mma16816h(oc[2*np + 1], pa[j], vv1);
            }
        }
        __syncthreads();
    }

    // ---- write output (fp16)
    float inv0 = 1.0f / l0, inv1 = 1.0f / l1;
    size_t r0 = (tokbase + w * 16 + group) * DD + h * DKK;
    size_t r1 = r0 + 8 * DD;
    #pragma unroll
    for (int i = 0; i < 8; i++) {
        int col = i * 8 + 2 * tig;
        __half2 o0 = __floats2half2_rn(oc[i][0] * inv0, oc[i][1] * inv0);
        __half2 o1 = __floats2half2_rn(oc[i][2] * inv1, oc[i][3] * inv1);
        *(uint32_t*)&O[r0 + col] = *(uint32_t*)&o0;
        *(uint32_t*)&O[r1 + col] = *(uint32_t*)&o1;
    }
}

// ---------------------------------------------------------------------------
// Launch
// ---------------------------------------------------------------------------
extern "C" void kernel_launch(void* const* d_in, const int* in_sizes, int n_in,
                              void* d_out, int out_size) {
    (void)in_sizes; (void)n_in; (void)out_size;

    const int*   ids  = (const int*)  d_in[0];
    const float* emb  = (const float*)d_in[1];
    const float* pe   = (const float*)d_in[2];
    const float* Wq   = (const float*)d_in[3];
    const float* Wk   = (const float*)d_in[4];
    const float* Wv   = (const float*)d_in[5];
    const float* Wo   = (const float*)d_in[6];
    const float* bo   = (const float*)d_in[7];
    const float* ln1s = (const float*)d_in[8];
    const float* ln1b = (const float*)d_in[9];
    const float* ln2s = (const float*)d_in[10];
    const float* ln2b = (const float*)d_in[11];
    const float* W1   = (const float*)d_in[12];
    const float* b1   = (const float*)d_in[13];
    const float* W2   = (const float*)d_in[14];
    const float* b2   = (const float*)d_in[15];
    const float* lnfs = (const float*)d_in[16];
    const float* lnfb = (const float*)d_in[17];
    float* out = (float*)d_out;

    float *x;
    __half *qkv, *hf, *af, *ff, *ef, *wf;
    cudaGetSymbolAddress((void**)&x,   g_x);
    cudaGetSymbolAddress((void**)&qkv, g_qkv);
    cudaGetSymbolAddress((void**)&hf,  g_hf);
    cudaGetSymbolAddress((void**)&af,  g_af);
    cudaGetSymbolAddress((void**)&ff,  g_ff);
    cudaGetSymbolAddress((void**)&ef,  g_ef);
    cudaGetSymbolAddress((void**)&wf,  g_wf);

    cudaFuncSetAttribute(gemm_f16<0>, cudaFuncAttributeMaxDynamicSharedMemorySize, SMEM_F16);
    cudaFuncSetAttribute(gemm_f16<1>, cudaFuncAttributeMaxDynamicSharedMemorySize, SMEM_F16);
    cudaFuncSetAttribute(gemm_f16<2>, cudaFuncAttributeMaxDynamicSharedMemorySize, SMEM_F16);
    cudaFuncSetAttribute(gemm_f16<3>, cudaFuncAttributeMaxDynamicSharedMemorySize, SMEM_F16);

    dim3 tb32(32, 8);
    {
        dim3 gQ(DD / 32, DD / 32, LL * 4);
        whalf_qkvo_kernel<<<gQ, tb32>>>(Wq, Wk, Wv, Wo, wf);
        dim3 g1(FFD / 32, DD / 32, LL);
        whalf_ff_kernel<<<g1, tb32>>>(W1, wf, DD, FFD, (size_t)4 * DD * DD);
        dim3 g2(DD / 32, FFD / 32, LL);
        whalf_ff_kernel<<<g2, tb32>>>(W2, wf, FFD, DD, (size_t)4 * DD * DD + (size_t)DD * FFD);
    }
    {
        int n4 = (VV * DD) / 4;
        ehalf_kernel<<<(n4 + 255) / 256, 256>>>(emb, ef, n4);
    }

    embed_kernel<<<NTOK, 256>>>(ids, emb, pe, x);

    dim3 gQKV(3 * DD / 128, NTOK / 128);  // 24 x 16
    dim3 gD(DD / 128, NTOK / 128);        // 8 x 16
    dim3 gF(FFD / 128, NTOK / 128);       // 32 x 16
    dim3 gV(VV / 128, NTOK / 128);        // 250 x 16
    dim3 gA(SS / 64, BB * HH);            // 8 x 64

    for (int l = 0; l < LL; l++) {
        __half* wqkv = wf + (size_t)l * WLAYER;         // [3*DD][DD]
        __half* wo   = wqkv + 3 * DD * DD;              // [DD][DD]
        __half* w1   = wo + DD * DD;                    // [FFD][DD]
        __half* w2   = w1 + (size_t)DD * FFD;           // [DD][FFD]

        ln_f16_kernel<<<NTOK, 256>>>(x, ln1s + l * DD, ln1b + l * DD, hf);
        gemm_f16<3><<<gQKV, 256, SMEM_F16>>>(hf, wqkv, nullptr, nullptr, nullptr, qkv, NTOK, 3 * DD, DD);
        fattn_kernel<<<gA, 128>>>(qkv, af);
        gemm_f16<1><<<gD, 256, SMEM_F16>>>(af, wo, bo + l * DD, x, x, nullptr, NTOK, DD, DD);

        ln_f16_kernel<<<NTOK, 256>>>(x, ln2s + l * DD, ln2b + l * DD, hf);
        gemm_f16<2><<<gF, 256, SMEM_F16>>>(hf, w1, b1 + l * FFD, nullptr, nullptr, ff, NTOK, FFD, DD);
        gemm_f16<1><<<gD, 256, SMEM_F16>>>(ff, w2, b2 + l * DD, x, x, nullptr, NTOK, DD, FFD);
    }

    ln_f16_kernel<<<NTOK, 256>>>(x, lnfs, lnfb, hf);
    gemm_f16<0><<<gV, 256, SMEM_F16>>>(hf, ef, nullptr, nullptr, out, nullptr, NTOK, VV, DD);
}

// round 17
// speedup vs baseline: 1.6154x; 1.0588x over previous
#include <cuda_runtime.h>
#include <cuda_fp16.h>
#include <math.h>
#include <stdint.h>

// Problem dims
#define BB   4
#define SS   512
#define DD   1024
#define HH   16
#define LL   6
#define FFD  4096
#define VV   32000
#define DKK  64
#define NTOK (BB*SS)   // 2048
#define RS   (3*DD)    // fused qkv row stride (halves)

// ---------------------------------------------------------------------------
// Scratch (device globals — no runtime allocation allowed)
// ---------------------------------------------------------------------------
__device__ float  g_x[NTOK*DD];
__device__ __half g_qkv[NTOK*3*DD];    // fused qkv, fp16
__device__ __half g_hf[NTOK*DD];       // LN out, fp16
__device__ __half g_af[NTOK*DD];       // attention out, fp16
__device__ __half g_ff[NTOK*FFD];      // GELU out, fp16
__device__ __half g_ef[(size_t)VV*DD]; // emb as fp16 (head B)

#define WLAYER (4*DD*DD + 2*DD*FFD)    // fp16 weights per layer (qkv,o,ff1,ff2)
__device__ __half g_wf[(size_t)LL*WLAYER];

__device__ __forceinline__ uint32_t smem_u32(const void* p) {
    uint32_t a;
    asm("{ .reg .u64 tmp; cvta.to.shared.u64 tmp, %1; cvt.u32.u64 %0, tmp; }"
        : "=r"(a) : "l"(p));
    return a;
}

// cp.async helpers
__device__ __forceinline__ void cp_async16(uint32_t dst, const void* src) {
    asm volatile("cp.async.cg.shared.global [%0], [%1], 16;" :: "r"(dst), "l"(src) : "memory");
}
__device__ __forceinline__ void cp_commit() {
    asm volatile("cp.async.commit_group;" ::: "memory");
}
template <int N>
__device__ __forceinline__ void cp_wait() {
    asm volatile("cp.async.wait_group %0;" :: "n"(N) : "memory");
}

__device__ __forceinline__ void ldsm_x4(unsigned& r0, unsigned& r1, unsigned& r2,
                                        unsigned& r3, uint32_t a) {
    asm volatile("ldmatrix.sync.aligned.m8n8.x4.shared.b16 {%0,%1,%2,%3}, [%4];"
                 : "=r"(r0), "=r"(r1), "=r"(r2), "=r"(r3) : "r"(a));
}
__device__ __forceinline__ void ldsm_x4_t(unsigned& r0, unsigned& r1, unsigned& r2,
                                          unsigned& r3, uint32_t a) {
    asm volatile("ldmatrix.sync.aligned.m8n8.x4.trans.shared.b16 {%0,%1,%2,%3}, [%4];"
                 : "=r"(r0), "=r"(r1), "=r"(r2), "=r"(r3) : "r"(a));
}

__device__ __forceinline__ void mma16816h(float* c, const unsigned* a, const unsigned* b) {
    asm volatile(
        "mma.sync.aligned.m16n8k16.row.col.f32.f16.f16.f32 "
        "{%0,%1,%2,%3}, {%4,%5,%6,%7}, {%8,%9}, {%0,%1,%2,%3};\n"
        : "+f"(c[0]), "+f"(c[1]), "+f"(c[2]), "+f"(c[3])
        : "r"(a[0]), "r"(a[1]), "r"(a[2]), "r"(a[3]), "r"(b[0]), "r"(b[1]));
}

// ---------------------------------------------------------------------------
// Shared LN math: given per-thread float4 of the row, produce stats + fp16 out
// (identical op order to the standalone LN kernel)
// ---------------------------------------------------------------------------
__device__ __forceinline__ void ln_reduce_write(float4 v, const float* __restrict__ s,
                                                const float* __restrict__ b,
                                                __half* __restrict__ y,
                                                int row, int t) {
    float s1 = v.x + v.y + v.z + v.w;
    float s2 = v.x*v.x + v.y*v.y + v.z*v.z + v.w*v.w;
    #pragma unroll
    for (int o = 16; o > 0; o >>= 1) {
        s1 += __shfl_xor_sync(0xffffffff, s1, o);
        s2 += __shfl_xor_sync(0xffffffff, s2, o);
    }
    __shared__ float a1[8], a2[8];
    if ((t & 31) == 0) { a1[t >> 5] = s1; a2[t >> 5] = s2; }
    __syncthreads();
    float m1 = 0.f, m2 = 0.f;
    #pragma unroll
    for (int i = 0; i < 8; i++) { m1 += a1[i]; m2 += a2[i]; }
    float mean = m1 * (1.0f / DD);
    float var  = m2 * (1.0f / DD) - mean * mean;
    float rstd = rsqrtf(var + 1e-5f);

    float4 sv = ((const float4*)s)[t];
    float4 bv = ((const float4*)b)[t];
    __half2 p0 = __floats2half2_rn((v.x - mean) * rstd * sv.x + bv.x,
                                   (v.y - mean) * rstd * sv.y + bv.y);
    __half2 p1 = __floats2half2_rn((v.z - mean) * rstd * sv.z + bv.z,
                                   (v.w - mean) * rstd * sv.w + bv.w);
    size_t o = (size_t)row * DD + t * 4;
    *(uint32_t*)&y[o]     = *(uint32_t*)&p0;
    *(uint32_t*)&y[o + 2] = *(uint32_t*)&p1;
}

// ---------------------------------------------------------------------------
// Embedding + batch-indexed positional encoding, fused with layer-0 LN1:
//   x[b,s,:] = emb[ids[b,s],:] + pe[b,:];  hf = LN(x; ln1_s[0], ln1_b[0])
// ---------------------------------------------------------------------------
__global__ void embed_ln_kernel(const int* __restrict__ ids,
                                const float* __restrict__ emb,
                                const float* __restrict__ pe,
                                const float* __restrict__ s,
                                const float* __restrict__ b,
                                float* __restrict__ x,
                                __half* __restrict__ y) {
    int row = blockIdx.x;
    int bb  = row / SS;
    int id  = ids[row];
    int t = threadIdx.x;
    float4 e = ((const float4*)(emb + (size_t)id * DD))[t];
    float4 p = ((const float4*)(pe  + (size_t)bb * DD))[t];
    float4 v = make_float4(e.x + p.x, e.y + p.y, e.z + p.z, e.w + p.w);
    ((float4*)(x + (size_t)row * DD))[t] = v;
    ln_reduce_write(v, s, b, y, row, t);
}

// ---------------------------------------------------------------------------
// LayerNorm (standalone): 1 float4/thread, warp-shuffle reduce, fp16 out
// ---------------------------------------------------------------------------
__global__ void ln_f16_kernel(const float* __restrict__ x,
                              const float* __restrict__ s,
                              const float* __restrict__ b,
                              __half* __restrict__ y) {
    int row = blockIdx.x;
    int t = threadIdx.x;
    float4 v = ((const float4*)(x + (size_t)row * DD))[t];
    ln_reduce_write(v, s, b, y, row, t);
}

// ---------------------------------------------------------------------------
// Weight conversion: transpose + fp16 (half2 stores), merged over layers
// ---------------------------------------------------------------------------
__device__ __forceinline__ void whalf_body(const float* __restrict__ W,
                                           __half* __restrict__ T, int K, int N) {
    __shared__ float tile[32][33];
    int n0 = blockIdx.x * 32, k0 = blockIdx.y * 32;
    int tx = threadIdx.x, ty = threadIdx.y;   // 32 x 8
    #pragma unroll
    for (int i = 0; i < 4; i++)
        tile[ty + i*8][tx] = W[(size_t)(k0 + ty + i*8) * N + n0 + tx];
    __syncthreads();
    int lin = tx + (ty << 5);
    #pragma unroll
    for (int rep = 0; rep < 2; rep++) {
        int idx = lin + rep * 256;
        int n  = idx >> 4;
        int kk = (idx & 15) << 1;
        __half2 p = __floats2half2_rn(tile[kk][n], tile[kk + 1][n]);
        *(__half2*)&T[(size_t)(n0 + n) * K + k0 + kk] = p;
    }
}

__global__ void whalf_qkvo_kernel(const float* __restrict__ Wq, const float* __restrict__ Wk,
                                  const float* __restrict__ Wv, const float* __restrict__ Wo,
                                  __half* __restrict__ T) {
    int z = blockIdx.z, l = z >> 2, widx = z & 3;
    const float* W = (widx == 0 ? Wq : widx == 1 ? Wk : widx == 2 ? Wv : Wo)
                     + (size_t)l * DD * DD;
    whalf_body(W, T + (size_t)l * WLAYER + (size_t)widx * DD * DD, DD, DD);
}

__global__ void whalf_ff_kernel(const float* __restrict__ W, __half* __restrict__ T,
                                int K, int N, size_t obase) {
    int l = blockIdx.z;
    whalf_body(W + (size_t)l * K * N, T + (size_t)l * WLAYER + obase, K, N);
}

// emb -> fp16 (vectorized)
__global__ void ehalf_kernel(const float* __restrict__ X, __half* __restrict__ Y, int n4) {
    int i = blockIdx.x * 256 + threadIdx.x;
    if (i < n4) {
        float4 v = ((const float4*)X)[i];
        ((__half2*)Y)[i * 2]     = __floats2half2_rn(v.x, v.y);
        ((__half2*)Y)[i * 2 + 1] = __floats2half2_rn(v.z, v.w);
    }
}

// ---------------------------------------------------------------------------
// fp16 GEMM (NT): C = A[M,K] @ B[N,K]^T
// 128x128 CTA tile, BK=64 (ROWB=144: 128B data + 16 pad), 256 threads,
// cp.async double-buffer + ldmatrix. K must be a multiple of 64.
// EPI 0: C = AB (+bias)        -> fp32  (head)
// EPI 1: C = Cin + AB + bias   -> fp32  (Wo, FF2 residual)
// EPI 2: gelu(AB + bias)       -> fp16  (FF1)
// EPI 3: C = AB                -> fp16  (QKV)
// ---------------------------------------------------------------------------
#define ROWB 144
#define MATB (128 * ROWB)               // 18432
#define H_STAGEB (2 * MATB)             // 36864
#define SMEM_F16 (2 * H_STAGEB)         // 73728 bytes

template <int EPI>
__global__ __launch_bounds__(256, 2)
void gemm_f16(const __half* __restrict__ A, const __half* __restrict__ B,
              const float* __restrict__ bias, const float* __restrict__ Cin,
              float* __restrict__ Cout, __half* __restrict__ Oh,
              int M, int N, int K) {
    extern __shared__ char smem[];
    uint32_t sb = smem_u32(smem);

    int t = threadIdx.x;
    int wid = t >> 5, lane = t & 31;
    int wm = wid >> 1, wn = wid & 1;
    int group = lane >> 2, tig = lane & 3;
    int m0 = blockIdx.y * 128, n0 = blockIdx.x * 128;

    float acc[2][8][4];
    #pragma unroll
    for (int i = 0; i < 2; i++)
        #pragma unroll
        for (int j = 0; j < 8; j++)
            #pragma unroll
            for (int kk = 0; kk < 4; kk++) acc[i][j][kk] = 0.f;

    const __half* srcs[2] = { A, B };

    auto load_stage = [&](int stage, int kt) {
        uint32_t base = sb + stage * H_STAGEB;
        int kofs = kt << 6;
        #pragma unroll
        for (int j = 0; j < 8; j++) {
            int lin = t + j * 256;           // 0..2047
            int mtx = lin >> 10;
            int c   = lin & 1023;
            int row = c >> 3, q = c & 7;
            int rbase = (mtx == 0) ? m0 : n0;
            const __half* src = srcs[mtx] + (size_t)(rbase + row) * K + kofs + q * 8;
            cp_async16(base + mtx * MATB + row * ROWB + q * 16, src);
        }
        cp_commit();
    };

    uint32_t aRow = (uint32_t)(wm * 32 + (lane & 15)) * ROWB;
    uint32_t aCol = (uint32_t)((lane >> 4) << 3) * 2;
    uint32_t bRowBase = (uint32_t)(wn * 64 + (lane & 7) + ((lane >> 4) << 3)) * ROWB;
    uint32_t bCol = (uint32_t)(((lane >> 3) & 1) << 3) * 2;

    const int nk = K >> 6;   // K-tiles of 64

    load_stage(0, 0);

    for (int i = 0; i < nk; i++) {
        if (i + 1 < nk) { load_stage((i + 1) & 1, i + 1); cp_wait<1>(); }
        else            { cp_wait<0>(); }
        __syncthreads();

        uint32_t stb = sb + (i & 1) * H_STAGEB;
        uint32_t pA = stb + aRow + aCol;
        uint32_t pB = stb + MATB + bRowBase + bCol;

        #pragma unroll
        for (int ks = 0; ks < 4; ks++) {
            uint32_t ko = ks * 32;          // 16 halves = 32 bytes per k-step
            unsigned af[2][4], bf[8][2];
            #pragma unroll
            for (int mt = 0; mt < 2; mt++) {
                ldsm_x4(af[mt][0], af[mt][1], af[mt][2], af[mt][3],
                        pA + (uint32_t)(mt * 16) * ROWB + ko);
            }
            #pragma unroll
            for (int jp = 0; jp < 4; jp++) {
                ldsm_x4(bf[2*jp][0], bf[2*jp][1], bf[2*jp+1][0], bf[2*jp+1][1],
                        pB + (uint32_t)(jp * 16) * ROWB + ko);
            }
            #pragma unroll
            for (int mt = 0; mt < 2; mt++)
                #pragma unroll
                for (int nt = 0; nt < 8; nt++)
                    mma16816h(acc[mt][nt], af[mt], bf[nt]);
        }
        if (i + 1 < nk) __syncthreads();
    }

    #pragma unroll
    for (int mt = 0; mt < 2; mt++) {
        #pragma unroll
        for (int nt = 0; nt < 8; nt++) {
            int col = n0 + wn * 64 + nt * 8 + tig * 2;
            float b0 = 0.f, b1v = 0.f;
            if (EPI != 3 && bias) { b0 = bias[col]; b1v = bias[col + 1]; }
            #pragma unroll
            for (int half = 0; half < 2; half++) {
                int row = m0 + wm * 32 + mt * 16 + group + half * 8;
                float v0 = acc[mt][nt][half * 2 + 0] + b0;
                float v1 = acc[mt][nt][half * 2 + 1] + b1v;
                size_t o = (size_t)row * N + col;
                if (EPI == 0) {
                    Cout[o] = v0; Cout[o + 1] = v1;
                } else if (EPI == 1) {
                    Cout[o] = Cin[o] + v0; Cout[o + 1] = Cin[o + 1] + v1;
                } else if (EPI == 2) {
                    float g0 = 0.5f * v0 * (1.0f + erff(v0 * 0.70710678118654752f));
                    float g1 = 0.5f * v1 * (1.0f + erff(v1 * 0.70710678118654752f));
                    __half2 p = __floats2half2_rn(g0, g1);
                    *(uint32_t*)&Oh[o] = *(uint32_t*)&p;
                } else {
                    __half2 p = __floats2half2_rn(v0, v1);
                    *(uint32_t*)&Oh[o] = *(uint32_t*)&p;
                }
            }
        }
    }
}

// ---------------------------------------------------------------------------
// Flash-style HMMA attention. CTA = (64-query tile, b, h); 4 warps x 16 rows.
// K/V tiles of 64 keys, cp.async double-buffered. Online softmax in regs.
// Rows are 64 halves = 128 data bytes; AROWB = 144 (128 + 16 pad).
// ---------------------------------------------------------------------------
#define AROWB 144
#define A_QOFF 0
#define A_TILE (64 * AROWB)            // 9216 bytes per matrix tile
#define A_STG  (2 * A_TILE)            // K+V per stage
#define A_KOFF(s) (A_TILE + (s) * A_STG)
#define A_VOFF(s) (A_TILE + (s) * A_STG + A_TILE)
#define A_SMEM (A_TILE + 2 * A_STG)    // 46080 bytes

__global__ __launch_bounds__(128)
void fattn_kernel(const __half* __restrict__ QKV, __half* __restrict__ O) {
    __shared__ char smem[A_SMEM];
    uint32_t sb = smem_u32(smem);

    int qt = blockIdx.x;               // 0..7 (64-query tiles)
    int bh = blockIdx.y;
    int b  = bh >> 4, h = bh & 15;
    int t  = threadIdx.x;
    int w  = t >> 5, lane = t & 31;
    int group = lane >> 2, tig = lane & 3;

    size_t tokbase = (size_t)(b * SS + qt * 64);

    // ---- prologue: load Q tile + K/V tile 0
    {
        #pragma unroll
        for (int j = 0; j < 4; j++) {      // Q: 512 chunks (64 rows x 8 x 16B)
            int lin = t + j * 128;
            int row = lin >> 3, q = lin & 7;
            const __half* src = QKV + (tokbase + row) * RS + h * DKK + q * 8;
            cp_async16(sb + A_QOFF + row * AROWB + q * 16, src);
        }
        #pragma unroll
        for (int j = 0; j < 8; j++) {      // K,V tile 0: 1024 chunks
            int lin = t + j * 128;
            int mtx = lin >> 9;
            int c   = lin & 511;
            int row = c >> 3, q = c & 7;
            const __half* src = QKV + (size_t)(b * SS + row) * RS + (1 + mtx) * DD + h * DKK + q * 8;
            cp_async16(sb + (mtx == 0 ? A_KOFF(0) : A_VOFF(0)) + row * AROWB + q * 16, src);
        }
        cp_commit();
    }

    // fragment addresses
    uint32_t qAddr = sb + A_QOFF + (uint32_t)(w * 16 + (lane & 15)) * AROWB
                   + (uint32_t)((lane >> 4) << 3) * 2;
    uint32_t kRowSel = (uint32_t)((lane & 7) + ((lane >> 4) << 3)) * AROWB
                     + (uint32_t)(((lane >> 3) & 1) << 3) * 2;
    uint32_t vRowSel = (uint32_t)((lane & 7) + (((lane >> 3) & 1) << 3)) * AROWB
                     + (uint32_t)((lane >> 4) << 3) * 2;

    float oc[8][4];
    #pragma unroll
    for (int i = 0; i < 8; i++)
        #pragma unroll
        for (int j = 0; j < 4; j++) oc[i][j] = 0.f;
    float m0 = -1e30f, m1 = -1e30f, l0 = 0.f, l1 = 0.f;

    const float scale = 0.125f;

    for (int kt = 0; kt <= qt; kt++) {
        if (kt < qt) {
            int s = (kt + 1) & 1;
            #pragma unroll
            for (int j = 0; j < 8; j++) {
                int lin = t + j * 128;
                int mtx = lin >> 9;
                int c   = lin & 511;
                int row = c >> 3, q = c & 7;
                const __half* src = QKV + (size_t)(b * SS + (kt + 1) * 64 + row) * RS
                                  + (1 + mtx) * DD + h * DKK + q * 8;
                cp_async16(sb + (mtx == 0 ? A_KOFF(s) : A_VOFF(s)) + row * AROWB + q * 16, src);
            }
            cp_commit();
            cp_wait<1>();
        } else {
            cp_wait<0>();
        }
        __syncthreads();

        int s = kt & 1;
        uint32_t kBase = sb + A_KOFF(s) + kRowSel;
        uint32_t vBase = sb + A_VOFF(s) + vRowSel;

        // ---- S = Q @ K^T  (16 rows x 64 keys per warp)
        float sc[8][4];
        #pragma unroll
        for (int i = 0; i < 8; i++)
            #pragma unroll
            for (int j = 0; j < 4; j++) sc[i][j] = 0.f;

        unsigned qf[4][4];
        #pragma unroll
        for (int ks = 0; ks < 4; ks++)
            ldsm_x4(qf[ks][0], qf[ks][1], qf[ks][2], qf[ks][3], qAddr + ks * 32);

        #pragma unroll
        for (int jp = 0; jp < 4; jp++) {
            #pragma unroll
            for (int ks = 0; ks < 4; ks++) {
                unsigned b0, b1, b2, b3;
                ldsm_x4(b0, b1, b2, b3, kBase + (uint32_t)(jp * 16) * AROWB + ks * 32);
                unsigned bb0[2] = { b0, b1 }, bb1[2] = { b2, b3 };
                mma16816h(sc[2*jp],     qf[ks], bb0);
                mma16816h(sc[2*jp + 1], qf[ks], bb1);
            }
        }

        // scale + causal mask (diagonal tile only)
        #pragma unroll
        for (int i = 0; i < 8; i++)
            #pragma unroll
            for (int e = 0; e < 4; e++) sc[i][e] *= scale;
        if (kt == qt) {
            #pragma unroll
            for (int i = 0; i < 8; i++) {
                #pragma unroll
                for (int e = 0; e < 4; e++) {
                    int key = i * 8 + 2 * tig + (e & 1);
                    int row = w * 16 + group + ((e >> 1) << 3);
                    if (key > row) sc[i][e] = -1e30f;
                }
            }
        }

        // online softmax (rows group / group+8; reduce over tig lanes)
        float rm0 = -1e30f, rm1 = -1e30f;
        #pragma unroll
        for (int i = 0; i < 8; i++) {
            rm0 = fmaxf(rm0, fmaxf(sc[i][0], sc[i][1]));
            rm1 = fmaxf(rm1, fmaxf(sc[i][2], sc[i][3]));
        }
        rm0 = fmaxf(rm0, __shfl_xor_sync(0xffffffff, rm0, 1));
        rm0 = fmaxf(rm0, __shfl_xor_sync(0xffffffff, rm0, 2));
        rm1 = fmaxf(rm1, __shfl_xor_sync(0xffffffff, rm1, 1));
        rm1 = fmaxf(rm1, __shfl_xor_sync(0xffffffff, rm1, 2));

        float mn0 = fmaxf(m0, rm0), mn1 = fmaxf(m1, rm1);
        float al0 = __expf(m0 - mn0), al1 = __expf(m1 - mn1);

        float rs0 = 0.f, rs1 = 0.f;
        unsigned pa[4][4];
        #pragma unroll
        for (int j = 0; j < 4; j++) {
            float p00 = __expf(sc[2*j][0] - mn0);
            float p01 = __expf(sc[2*j][1] - mn0);
            float p10 = __expf(sc[2*j][2] - mn1);
            float p11 = __expf(sc[2*j][3] - mn1);
            float q00 = __expf(sc[2*j+1][0] - mn0);
            float q01 = __expf(sc[2*j+1][1] - mn0);
            float q10 = __expf(sc[2*j+1][2] - mn1);
            float q11 = __expf(sc[2*j+1][3] - mn1);
            rs0 += p00 + p01 + q00 + q01;
            rs1 += p10 + p11 + q10 + q11;
            __half2 h0 = __floats2half2_rn(p00, p01);
            __half2 h1 = __floats2half2_rn(p10, p11);
            __half2 h2 = __floats2half2_rn(q00, q01);
            __half2 h3 = __floats2half2_rn(q10, q11);
            pa[j][0] = *(unsigned*)&h0;
            pa[j][1] = *(unsigned*)&h1;
            pa[j][2] = *(unsigned*)&h2;
            pa[j][3] = *(unsigned*)&h3;
        }
        rs0 += __shfl_xor_sync(0xffffffff, rs0, 1);
        rs0 += __shfl_xor_sync(0xffffffff, rs0, 2);
        rs1 += __shfl_xor_sync(0xffffffff, rs1, 1);
        rs1 += __shfl_xor_sync(0xffffffff, rs1, 2);

        l0 = l0 * al0 + rs0;
        l1 = l1 * al1 + rs1;
        m0 = mn0; m1 = mn1;

        #pragma unroll
        for (int i = 0; i < 8; i++) {
            oc[i][0] *= al0; oc[i][1] *= al0;
            oc[i][2] *= al1; oc[i][3] *= al1;
        }

        // ---- O += P @ V   (V^T fragments via ldmatrix.trans)
        #pragma unroll
        for (int j = 0; j < 4; j++) {
            #pragma unroll
            for (int np = 0; np < 4; np++) {
                unsigned v0, v1, v2, v3;
                ldsm_x4_t(v0, v1, v2, v3,
                          vBase + (uint32_t)(j * 16) * AROWB + (uint32_t)(np * 16) * 2);
                unsigned vv0[2] = { v0, v1 }, vv1[2] = { v2, v3 };
                mma16816h(oc[2*np],     pa[j], vv0);
                mma16816h(oc[2*np + 1], pa[j], vv1);
            }
        }
        if (kt < qt) __syncthreads();   // final iteration: nothing touches smem after
    }

    // ---- write output (fp16)
    float inv0 = 1.0f / l0, inv1 = 1.0f / l1;
    size_t r0 = (tokbase + w * 16 + group) * DD + h * DKK;
    size_t r1 = r0 + 8 * DD;
    #pragma unroll
    for (int i = 0; i < 8; i++) {
        int col = i * 8 + 2 * tig;
        __half2 o0 = __floats2half2_rn(oc[i][0] * inv0, oc[i][1] * inv0);
        __half2 o1 = __floats2half2_rn(oc[i][2] * inv1, oc[i][3] * inv1);
        *(uint32_t*)&O[r0 + col] = *(uint32_t*)&o0;
        *(uint32_t*)&O[r1 + col] = *(uint32_t*)&o1;
    }
}

// ---------------------------------------------------------------------------
// Launch
// ---------------------------------------------------------------------------
extern "C" void kernel_launch(void* const* d_in, const int* in_sizes, int n_in,
                              void* d_out, int out_size) {
    (void)in_sizes; (void)n_in; (void)out_size;

    const int*   ids  = (const int*)  d_in[0];
    const float* emb  = (const float*)d_in[1];
    const float* pe   = (const float*)d_in[2];
    const float* Wq   = (const float*)d_in[3];
    const float* Wk   = (const float*)d_in[4];
    const float* Wv   = (const float*)d_in[5];
    const float* Wo   = (const float*)d_in[6];
    const float* bo   = (const float*)d_in[7];
    const float* ln1s = (const float*)d_in[8];
    const float* ln1b = (const float*)d_in[9];
    const float* ln2s = (const float*)d_in[10];
    const float* ln2b = (const float*)d_in[11];
    const float* W1   = (const float*)d_in[12];
    const float* b1   = (const float*)d_in[13];
    const float* W2   = (const float*)d_in[14];
    const float* b2   = (const float*)d_in[15];
    const float* lnfs = (const float*)d_in[16];
    const float* lnfb = (const float*)d_in[17];
    float* out = (float*)d_out;

    float *x;
    __half *qkv, *hf, *af, *ff, *ef, *wf;
    cudaGetSymbolAddress((void**)&x,   g_x);
    cudaGetSymbolAddress((void**)&qkv, g_qkv);
    cudaGetSymbolAddress((void**)&hf,  g_hf);
    cudaGetSymbolAddress((void**)&af,  g_af);
    cudaGetSymbolAddress((void**)&ff,  g_ff);
    cudaGetSymbolAddress((void**)&ef,  g_ef);
    cudaGetSymbolAddress((void**)&wf,  g_wf);

    cudaFuncSetAttribute(gemm_f16<0>, cudaFuncAttributeMaxDynamicSharedMemorySize, SMEM_F16);
    cudaFuncSetAttribute(gemm_f16<1>, cudaFuncAttributeMaxDynamicSharedMemorySize, SMEM_F16);
    cudaFuncSetAttribute(gemm_f16<2>, cudaFuncAttributeMaxDynamicSharedMemorySize, SMEM_F16);
    cudaFuncSetAttribute(gemm_f16<3>, cudaFuncAttributeMaxDynamicSharedMemorySize, SMEM_F16);

    dim3 tb32(32, 8);
    {
        dim3 gQ(DD / 32, DD / 32, LL * 4);
        whalf_qkvo_kernel<<<gQ, tb32>>>(Wq, Wk, Wv, Wo, wf);
        dim3 g1(FFD / 32, DD / 32, LL);
        whalf_ff_kernel<<<g1, tb32>>>(W1, wf, DD, FFD, (size_t)4 * DD * DD);
        dim3 g2(DD / 32, FFD / 32, LL);
        whalf_ff_kernel<<<g2, tb32>>>(W2, wf, FFD, DD, (size_t)4 * DD * DD + (size_t)DD * FFD);
    }
    {
        int n4 = (VV * DD) / 4;
        ehalf_kernel<<<(n4 + 255) / 256, 256>>>(emb, ef, n4);
    }

    // embed fused with layer-0 LN1
    embed_ln_kernel<<<NTOK, 256>>>(ids, emb, pe, ln1s, ln1b, x, hf);

    dim3 gQKV(3 * DD / 128, NTOK / 128);  // 24 x 16
    dim3 gD(DD / 128, NTOK / 128);        // 8 x 16
    dim3 gF(FFD / 128, NTOK / 128);       // 32 x 16
    dim3 gV(VV / 128, NTOK / 128);        // 250 x 16
    dim3 gA(SS / 64, BB * HH);            // 8 x 64

    for (int l = 0; l < LL; l++) {
        __half* wqkv = wf + (size_t)l * WLAYER;         // [3*DD][DD]
        __half* wo   = wqkv + 3 * DD * DD;              // [DD][DD]
        __half* w1   = wo + DD * DD;                    // [FFD][DD]
        __half* w2   = w1 + (size_t)DD * FFD;           // [DD][FFD]

        if (l > 0)
            ln_f16_kernel<<<NTOK, 256>>>(x, ln1s + l * DD, ln1b + l * DD, hf);
        gemm_f16<3><<<gQKV, 256, SMEM_F16>>>(hf, wqkv, nullptr, nullptr, nullptr, qkv, NTOK, 3 * DD, DD);
        fattn_kernel<<<gA, 128>>>(qkv, af);
        gemm_f16<1><<<gD, 256, SMEM_F16>>>(af, wo, bo + l * DD, x, x, nullptr, NTOK, DD, DD);

        ln_f16_kernel<<<NTOK, 256>>>(x, ln2s + l * DD, ln2b + l * DD, hf);
        gemm_f16<2><<<gF, 256, SMEM_F16>>>(hf, w1, b1 + l * FFD, nullptr, nullptr, ff, NTOK, FFD, DD);
        gemm_f16<1><<<gD, 256, SMEM_F16>>>(ff, w2, b2 + l * DD, x, x, nullptr, NTOK, DD, FFD);
    }

    ln_f16_kernel<<<NTOK, 256>>>(x, lnfs, lnfb, hf);
    gemm_f16<0><<<gV, 256, SMEM_F16>>>(hf, ef, nullptr, nullptr, out, nullptr, NTOK, VV, DD);
}